// round 3
// baseline (speedup 1.0000x reference)
#include <cuda_runtime.h>
#include <cuda_bf16.h>
#include <cstdint>

#define NN 8192
#define DD 128
#define LOG2E 1.4426950408889634f

// ---------------- device scratch (static allocation only) ----------------
__device__ __nv_bfloat16 g_a[NN * DD];   // a in bf16
__device__ __nv_bfloat16 g_bs[NN * DD];  // b * log2(e) in bf16
__device__ float g_V[NN];
__device__ float g_sum;
__device__ int   g_cnt;

// ---------------- helpers ----------------
__device__ __forceinline__ float ex2f(float x) {
    float y;
    asm("ex2.approx.f32 %0, %1;" : "=f"(y) : "f"(x));
    return y;
}

__device__ __forceinline__ void mma16816(float c[4], const uint32_t a[4], const uint32_t b[2]) {
    asm volatile(
        "mma.sync.aligned.m16n8k16.row.col.f32.bf16.bf16.f32 "
        "{%0,%1,%2,%3}, {%4,%5,%6,%7}, {%8,%9}, {%0,%1,%2,%3};\n"
        : "+f"(c[0]), "+f"(c[1]), "+f"(c[2]), "+f"(c[3])
        : "r"(a[0]), "r"(a[1]), "r"(a[2]), "r"(a[3]),
          "r"(b[0]), "r"(b[1]));
}

// ---------------- kernel 0: convert + zero ----------------
__global__ void prep_kernel(const float* __restrict__ a, const float* __restrict__ b) {
    int i = blockIdx.x * blockDim.x + threadIdx.x;
    if (i < NN * DD) {
        g_a[i]  = __float2bfloat16(a[i]);
        g_bs[i] = __float2bfloat16(b[i] * LOG2E);
    }
    if (i < NN) g_V[i] = 0.0f;
    if (i == 0) { g_sum = 0.0f; g_cnt = 0; }
}

// ---------------- kernel 1: V[i] = sum_{label_j != label_i} exp(1 + a_i.b_j) ----
// Grid: (64 row-tiles, JCHUNKS j-chunks). CTA = 256 threads = 8 warps.
// CTA tile 128 rows x 128 cols. Warp tile: 32 rows (wm) x 64 cols (wn).
#define JCHUNKS 16
__global__ __launch_bounds__(256, 1) void pass1_kernel(const int* __restrict__ labels) {
    __shared__ __nv_bfloat16 sB[128][136];  // padded: conflict-free frag loads
    __shared__ int sLbl[128];

    const int tid  = threadIdx.x;
    const int w    = tid >> 5;
    const int lane = tid & 31;
    const int g    = lane >> 2;   // group id (row within 8)
    const int t    = lane & 3;    // thread-in-group (col pair)
    const int wm   = w & 3;       // warp row idx (0..3) -> rows 32*wm
    const int wn   = w >> 2;      // warp col idx (0..1) -> cols 64*wn
    const int row_base = blockIdx.x * 128 + wm * 32;
    const int chunk    = blockIdx.y;

    // A fragments: registers for the whole kernel (K=128 -> 8 k-steps, 2 m-tiles)
    uint32_t afr[2][8][4];
    const uint32_t* Aw = reinterpret_cast<const uint32_t*>(g_a);  // bf16x2 words, 64/row
#pragma unroll
    for (int mt = 0; mt < 2; mt++) {
        const int r0 = row_base + 16 * mt + g;
        const int r1 = r0 + 8;
#pragma unroll
        for (int kk = 0; kk < 8; kk++) {
            const int cw = kk * 8 + t;  // word index of k-col pair
            afr[mt][kk][0] = Aw[r0 * 64 + cw];
            afr[mt][kk][1] = Aw[r1 * 64 + cw];
            afr[mt][kk][2] = Aw[r0 * 64 + cw + 4];
            afr[mt][kk][3] = Aw[r1 * 64 + cw + 4];
        }
    }
    // row labels for this thread's 4 row slots
    int lr[2][2];
    lr[0][0] = labels[row_base + g];
    lr[0][1] = labels[row_base + g + 8];
    lr[1][0] = labels[row_base + 16 + g];
    lr[1][1] = labels[row_base + 16 + g + 8];

    float vacc[2][2] = {{0.f, 0.f}, {0.f, 0.f}};

    for (int jt = chunk; jt < 64; jt += JCHUNKS) {
        const int j0 = jt * 128;
        // stage FULL B tile (128 rows x 128 bf16 = 32 KB): 2 threads/row,
        // each thread copies 128 bytes (8 x uint4). Every smem byte written.
        {
            const int r = tid >> 1, h = tid & 1;
            const uint4* src = reinterpret_cast<const uint4*>(g_bs + (j0 + r) * 128 + h * 64);
            uint4* dst = reinterpret_cast<uint4*>(&sB[r][h * 64]);
#pragma unroll
            for (int q = 0; q < 8; q++) dst[q] = src[q];
        }
        if (tid < 128) sLbl[tid] = labels[j0 + tid];
        __syncthreads();

#pragma unroll
        for (int nt = 0; nt < 8; nt++) {
            const int n = wn * 64 + nt * 8 + g;  // j index within tile (B column of S)
            uint32_t bfr[8][2];
#pragma unroll
            for (int kk = 0; kk < 8; kk++) {
                bfr[kk][0] = *reinterpret_cast<const uint32_t*>(&sB[n][kk * 16 + 2 * t]);
                bfr[kk][1] = *reinterpret_cast<const uint32_t*>(&sB[n][kk * 16 + 2 * t + 8]);
            }
            float C[2][4] = {{0.f, 0.f, 0.f, 0.f}, {0.f, 0.f, 0.f, 0.f}};
#pragma unroll
            for (int kk = 0; kk < 8; kk++) {
                mma16816(C[0], afr[0][kk], bfr[kk]);
                mma16816(C[1], afr[1][kk], bfr[kk]);
            }
            // epilogue: masked exp2 accumulate (C already = S * log2e)
            const int c0  = wn * 64 + nt * 8 + 2 * t;
            const int lc0 = sLbl[c0];
            const int lc1 = sLbl[c0 + 1];
#pragma unroll
            for (int mt = 0; mt < 2; mt++) {
                if (lr[mt][0] != lc0) vacc[mt][0] += ex2f(C[mt][0] + LOG2E);
                if (lr[mt][0] != lc1) vacc[mt][0] += ex2f(C[mt][1] + LOG2E);
                if (lr[mt][1] != lc0) vacc[mt][1] += ex2f(C[mt][2] + LOG2E);
                if (lr[mt][1] != lc1) vacc[mt][1] += ex2f(C[mt][3] + LOG2E);
            }
        }
        __syncthreads();
    }

    // reduce across the 4 threads of each group (same rows, different cols)
#pragma unroll
    for (int mt = 0; mt < 2; mt++) {
#pragma unroll
        for (int h = 0; h < 2; h++) {
            float v = vacc[mt][h];
            v += __shfl_xor_sync(0xffffffffu, v, 1);
            v += __shfl_xor_sync(0xffffffffu, v, 2);
            if (t == 0) atomicAdd(&g_V[row_base + 16 * mt + 8 * h + g], v);
        }
    }
}

// ---------------- kernel 2: positive pairs hinge ----------------
// Grid: 1024 blocks x 256 threads. Each block owns 8 rows i.
#define P2_ROWS 8
#define P2_CAP 2048
__global__ __launch_bounds__(256) void pass2_kernel(const float* __restrict__ a,
                                                    const float* __restrict__ b,
                                                    const int* __restrict__ labels) {
    __shared__ float sA[P2_ROWS][DD];
    __shared__ int   sLr[P2_ROWS];
    __shared__ float sVr[P2_ROWS];
    __shared__ int2  list[P2_CAP];
    __shared__ int   cnt;
    __shared__ float wsum[8];

    const int tid = threadIdx.x;
    const int i0  = blockIdx.x * P2_ROWS;
    if (tid == 0) cnt = 0;
    if (tid < P2_ROWS) { sLr[tid] = labels[i0 + tid]; sVr[tid] = g_V[i0 + tid]; }
    for (int k = tid; k < P2_ROWS * DD; k += 256)
        sA[k >> 7][k & 127] = a[(i0 + (k >> 7)) * DD + (k & 127)];
    __syncthreads();

    // scan all labels, collect positive ordered pairs (i, j), j != i
    for (int j = tid; j < NN; j += 256) {
        const int lj = labels[j];
#pragma unroll
        for (int r = 0; r < P2_ROWS; r++) {
            if (lj == sLr[r] && j != i0 + r) {
                int p = atomicAdd(&cnt, 1);
                if (p < P2_CAP) list[p] = make_int2(r, j);
            }
        }
    }
    __syncthreads();
    const int n = (cnt < P2_CAP) ? cnt : P2_CAP;

    const int w = tid >> 5, lane = tid & 31;
    float lsum = 0.0f;
    for (int p = w; p < n; p += 8) {
        const int r = list[p].x, j = list[p].y;
        const float4 b4 = reinterpret_cast<const float4*>(b + j * DD)[lane];
        float dot = sA[r][lane * 4 + 0] * b4.x + sA[r][lane * 4 + 1] * b4.y +
                    sA[r][lane * 4 + 2] * b4.z + sA[r][lane * 4 + 3] * b4.w;
#pragma unroll
        for (int o = 16; o > 0; o >>= 1) dot += __shfl_xor_sync(0xffffffffu, dot, o);
        if (lane == 0) {
            float h = logf(sVr[r] + g_V[j]) - dot;
            h = fmaxf(h, 0.0f);
            lsum += h * h;
        }
    }
    if (lane == 0) wsum[w] = lsum;
    __syncthreads();
    if (tid == 0) {
        float s = 0.0f;
#pragma unroll
        for (int k = 0; k < 8; k++) s += wsum[k];
        atomicAdd(&g_sum, s);
        atomicAdd(&g_cnt, n);
    }
}

// ---------------- kernel 3: finalize ----------------
__global__ void finalize_kernel(float* __restrict__ out) {
    out[0] = g_sum / (2.0f * (float)g_cnt);
}

// ---------------- launch ----------------
extern "C" void kernel_launch(void* const* d_in, const int* in_sizes, int n_in,
                              void* d_out, int out_size) {
    const float* a      = (const float*)d_in[0];
    const float* b      = (const float*)d_in[1];
    const int*   labels = (const int*)d_in[2];
    float* out = (float*)d_out;

    prep_kernel<<<(NN * DD + 255) / 256, 256>>>(a, b);
    pass1_kernel<<<dim3(64, JCHUNKS), 256>>>(labels);
    pass2_kernel<<<NN / P2_ROWS, 256>>>(a, b, labels);
    finalize_kernel<<<1, 1>>>(out);
}

// round 5
// speedup vs baseline: 1.2182x; 1.2182x over previous
#include <cuda_runtime.h>
#include <cuda_bf16.h>
#include <cstdint>

#define NN 8192
#define DD 128
#define LOG2E 1.4426950408889634f
#define E1 2.718281828459045f
#define NCLS 1024

// ---------------- device scratch (static allocation only) ----------------
__device__ __nv_bfloat16 g_a[NN * DD];   // a in bf16
__device__ __nv_bfloat16 g_bs[NN * DD];  // b * log2(e) in bf16
__device__ float g_V[NN];                // raw row sums: sum_all_j 2^(S*log2e)
__device__ float g_sum;
__device__ int   g_cnt;
__device__ int   g_done;

// ---------------- helpers ----------------
__device__ __forceinline__ float ex2f(float x) {
    float y;
    asm("ex2.approx.f32 %0, %1;" : "=f"(y) : "f"(x));
    return y;
}

__device__ __forceinline__ void mma16816(float c[4], const uint32_t a[4], const uint32_t b[2]) {
    asm volatile(
        "mma.sync.aligned.m16n8k16.row.col.f32.bf16.bf16.f32 "
        "{%0,%1,%2,%3}, {%4,%5,%6,%7}, {%8,%9}, {%0,%1,%2,%3};\n"
        : "+f"(c[0]), "+f"(c[1]), "+f"(c[2]), "+f"(c[3])
        : "r"(a[0]), "r"(a[1]), "r"(a[2]), "r"(a[3]),
          "r"(b[0]), "r"(b[1]));
}

// ---------------- kernel 0: convert + zero (vectorized x4) ----------------
__global__ void prep_kernel(const float* __restrict__ a, const float* __restrict__ b) {
    int i = blockIdx.x * blockDim.x + threadIdx.x;   // 0 .. NN*DD/4
    if (i < NN * DD / 4) {
        float4 av = reinterpret_cast<const float4*>(a)[i];
        float4 bv = reinterpret_cast<const float4*>(b)[i];
        __nv_bfloat162* pa = reinterpret_cast<__nv_bfloat162*>(g_a);
        __nv_bfloat162* pb = reinterpret_cast<__nv_bfloat162*>(g_bs);
        pa[2 * i + 0] = __floats2bfloat162_rn(av.x, av.y);
        pa[2 * i + 1] = __floats2bfloat162_rn(av.z, av.w);
        pb[2 * i + 0] = __floats2bfloat162_rn(bv.x * LOG2E, bv.y * LOG2E);
        pb[2 * i + 1] = __floats2bfloat162_rn(bv.z * LOG2E, bv.w * LOG2E);
    }
    if (i < NN) g_V[i] = 0.0f;
    if (i == 0) { g_sum = 0.0f; g_cnt = 0; g_done = 0; }
}

// ---------------- kernel 1: T[i] = sum_ALL_j 2^(a_i . bs_j)  (no masks) ----
// Grid: (64 row-tiles, JCHUNKS). CTA = 256 threads = 8 warps, 2 CTAs/SM.
// CTA tile 128 rows x 128 cols. Warp tile 32 rows (wm 0..3) x 64 cols (wn 0..1).
#define JCHUNKS 9
__global__ __launch_bounds__(256, 2) void pass1_kernel() {
    __shared__ __nv_bfloat16 sB[128][136];  // padded: conflict-free frag loads

    const int tid  = threadIdx.x;
    const int w    = tid >> 5;
    const int lane = tid & 31;
    const int g    = lane >> 2;   // row-in-8
    const int t    = lane & 3;    // col pair
    const int wm   = w & 3;
    const int wn   = w >> 2;
    const int row_base = blockIdx.x * 128 + wm * 32;
    const int chunk    = blockIdx.y;

    // A fragments resident in registers (K=128 -> 8 k-steps, 2 m-tiles)
    uint32_t afr[2][8][4];
    const uint32_t* Aw = reinterpret_cast<const uint32_t*>(g_a);  // bf16x2 words
#pragma unroll
    for (int mt = 0; mt < 2; mt++) {
        const int r0 = row_base + 16 * mt + g;
        const int r1 = r0 + 8;
#pragma unroll
        for (int kk = 0; kk < 8; kk++) {
            const int cw = kk * 8 + t;
            afr[mt][kk][0] = Aw[r0 * 64 + cw];
            afr[mt][kk][1] = Aw[r1 * 64 + cw];
            afr[mt][kk][2] = Aw[r0 * 64 + cw + 4];
            afr[mt][kk][3] = Aw[r1 * 64 + cw + 4];
        }
    }

    float vacc[2][2] = {{0.f, 0.f}, {0.f, 0.f}};

    for (int jt = chunk; jt < 64; jt += JCHUNKS) {
        const int j0 = jt * 128;
        // stage full B tile (128 x 128 bf16 = 32 KB): 2 threads/row, 128B each
        {
            const int r = tid >> 1, h = tid & 1;
            const uint4* src = reinterpret_cast<const uint4*>(g_bs + (j0 + r) * 128 + h * 64);
            uint4* dst = reinterpret_cast<uint4*>(&sB[r][h * 64]);
#pragma unroll
            for (int q = 0; q < 8; q++) dst[q] = src[q];
        }
        __syncthreads();

#pragma unroll
        for (int nt = 0; nt < 8; nt++) {
            const int n = wn * 64 + nt * 8 + g;
            uint32_t bfr[8][2];
#pragma unroll
            for (int kk = 0; kk < 8; kk++) {
                bfr[kk][0] = *reinterpret_cast<const uint32_t*>(&sB[n][kk * 16 + 2 * t]);
                bfr[kk][1] = *reinterpret_cast<const uint32_t*>(&sB[n][kk * 16 + 2 * t + 8]);
            }
            float C[2][4] = {{0.f, 0.f, 0.f, 0.f}, {0.f, 0.f, 0.f, 0.f}};
#pragma unroll
            for (int kk = 0; kk < 8; kk++) {
                mma16816(C[0], afr[0][kk], bfr[kk]);
                mma16816(C[1], afr[1][kk], bfr[kk]);
            }
            // unmasked: T accumulates every term (C = S * log2e)
            vacc[0][0] += ex2f(C[0][0]) + ex2f(C[0][1]);
            vacc[0][1] += ex2f(C[0][2]) + ex2f(C[0][3]);
            vacc[1][0] += ex2f(C[1][0]) + ex2f(C[1][1]);
            vacc[1][1] += ex2f(C[1][2]) + ex2f(C[1][3]);
        }
        __syncthreads();
    }

    // reduce across the 4 threads of each group (same rows, different cols)
#pragma unroll
    for (int mt = 0; mt < 2; mt++) {
#pragma unroll
        for (int h = 0; h < 2; h++) {
            float v = vacc[mt][h];
            v += __shfl_xor_sync(0xffffffffu, v, 1);
            v += __shfl_xor_sync(0xffffffffu, v, 2);
            if (t == 0) atomicAdd(&g_V[row_base + 16 * mt + 8 * h + g], v);
        }
    }
}

// ---------------- kernel 2: per-class correction + hinge ----------------
// One block per class. Positive pairs are intra-class, so V for both ends of
// every pair is produced inside this block. Last block writes the final loss.
#define MAXM 40
__global__ __launch_bounds__(256) void pass2_kernel(const float* __restrict__ a,
                                                    const float* __restrict__ b,
                                                    const int* __restrict__ labels,
                                                    float* __restrict__ out) {
    __shared__ float sa[MAXM][DD];
    __shared__ float sb[MAXM][DD];
    __shared__ float sD[MAXM][MAXM];
    __shared__ float sV[MAXM];
    __shared__ int   sidx[MAXM];
    __shared__ int   cnt;
    __shared__ float wsum[8];

    const int tid = threadIdx.x;
    const int c   = blockIdx.x;
    if (tid == 0) cnt = 0;
    __syncthreads();

    // gather members of class c
    for (int j = tid; j < NN; j += 256) {
        if (labels[j] == c) {
            int p = atomicAdd(&cnt, 1);
            if (p < MAXM) sidx[p] = j;
        }
    }
    __syncthreads();
    const int m = (cnt < MAXM) ? cnt : MAXM;

    if (m > 0) {
        // load member rows of a and b (fp32 exact)
        for (int k = tid; k < m * 32; k += 256) {
            const int r = k >> 5, q = k & 31;
            reinterpret_cast<float4*>(sa[r])[q] = reinterpret_cast<const float4*>(a + sidx[r] * DD)[q];
            reinterpret_cast<float4*>(sb[r])[q] = reinterpret_cast<const float4*>(b + sidx[r] * DD)[q];
        }
        __syncthreads();

        // all m x m dots (including diagonal, needed for V correction)
        const int w = tid >> 5, lane = tid & 31;
        for (int p = w; p < m * m; p += 8) {
            const int i = p / m, j = p % m;
            const float4 av = reinterpret_cast<const float4*>(sa[i])[lane];
            const float4 bv = reinterpret_cast<const float4*>(sb[j])[lane];
            float dot = av.x * bv.x + av.y * bv.y + av.z * bv.z + av.w * bv.w;
#pragma unroll
            for (int o = 16; o > 0; o >>= 1) dot += __shfl_xor_sync(0xffffffffu, dot, o);
            if (lane == 0) sD[i][j] = dot;
        }
        __syncthreads();

        // corrected V: V = e * (T - sum_{j in class} 2^(D*log2e))
        if (tid < m) {
            float corr = 0.0f;
            for (int j = 0; j < m; j++) corr += ex2f(sD[tid][j] * LOG2E);
            sV[tid] = E1 * (g_V[sidx[tid]] - corr);
        }
        __syncthreads();

        // hinge over ordered positive pairs (i != j)
        float lsum = 0.0f;
        for (int p = tid; p < m * m; p += 256) {
            const int i = p / m, j = p % m;
            if (i != j) {
                float h = fmaxf(logf(sV[i] + sV[j]) - sD[i][j], 0.0f);
                lsum += h * h;
            }
        }
#pragma unroll
        for (int o = 16; o > 0; o >>= 1) lsum += __shfl_xor_sync(0xffffffffu, lsum, o);
        if (lane == 0) wsum[w] = lsum;
        __syncthreads();
        if (tid == 0) {
            float s = 0.0f;
#pragma unroll
            for (int k = 0; k < 8; k++) s += wsum[k];
            atomicAdd(&g_sum, s);
            atomicAdd(&g_cnt, m * (m - 1));
        }
    }

    // last block computes the final scalar
    if (tid == 0) {
        __threadfence();
        if (atomicAdd(&g_done, 1) == NCLS - 1) {
            __threadfence();
            float s = atomicAdd(&g_sum, 0.0f);
            int   n = atomicAdd(&g_cnt, 0);
            out[0] = s / (2.0f * (float)n);
        }
    }
}

// ---------------- launch ----------------
extern "C" void kernel_launch(void* const* d_in, const int* in_sizes, int n_in,
                              void* d_out, int out_size) {
    const float* a      = (const float*)d_in[0];
    const float* b      = (const float*)d_in[1];
    const int*   labels = (const int*)d_in[2];
    float* out = (float*)d_out;

    prep_kernel<<<(NN * DD / 4 + 255) / 256, 256>>>(a, b);
    pass1_kernel<<<dim3(64, JCHUNKS), 256>>>();
    pass2_kernel<<<NCLS, 256>>>(a, b, labels, out);
}

// round 7
// speedup vs baseline: 1.6619x; 1.3642x over previous
#include <cuda_runtime.h>
#include <cuda_bf16.h>
#include <cstdint>

#define NN 8192
#define DD 128
#define LOG2E 1.4426950408889634f
#define E1 2.718281828459045f
#define NCLS 1024

// ---------------- device scratch (static allocation only) ----------------
__device__ __nv_bfloat16 g_a[NN * DD];   // a in bf16
__device__ __nv_bfloat16 g_bs[NN * DD];  // b * log2(e) in bf16
__device__ float g_V[NN];                // raw row sums: sum_all_j 2^(S*log2e)
__device__ float g_sum;
__device__ int   g_cnt;
__device__ int   g_done;

// ---------------- helpers ----------------
__device__ __forceinline__ uint32_t smem_u32(const void* p) {
    uint32_t a;
    asm("{ .reg .u64 t; cvta.to.shared.u64 t, %1; cvt.u32.u64 %0, t; }" : "=r"(a) : "l"(p));
    return a;
}
__device__ __forceinline__ float ex2f(float x) {
    float y;
    asm("ex2.approx.f32 %0, %1;" : "=f"(y) : "f"(x));
    return y;
}
__device__ __forceinline__ void mma16816(float c[4], const uint32_t a[4], const uint32_t b0, const uint32_t b1) {
    asm volatile(
        "mma.sync.aligned.m16n8k16.row.col.f32.bf16.bf16.f32 "
        "{%0,%1,%2,%3}, {%4,%5,%6,%7}, {%8,%9}, {%0,%1,%2,%3};\n"
        : "+f"(c[0]), "+f"(c[1]), "+f"(c[2]), "+f"(c[3])
        : "r"(a[0]), "r"(a[1]), "r"(a[2]), "r"(a[3]),
          "r"(b0), "r"(b1));
}

#define CP_ASYNC16(dst, src) asm volatile("cp.async.cg.shared.global [%0], [%1], 16;" :: "r"(dst), "l"(src) : "memory")
#define CP_COMMIT()          asm volatile("cp.async.commit_group;" ::: "memory")
#define CP_WAIT(n)           asm volatile("cp.async.wait_group %0;" :: "n"(n) : "memory")

// ---------------- kernel 0: convert + zero (vectorized x4) ----------------
__global__ void prep_kernel(const float* __restrict__ a, const float* __restrict__ b) {
    int i = blockIdx.x * blockDim.x + threadIdx.x;   // 0 .. NN*DD/4
    if (i < NN * DD / 4) {
        float4 av = reinterpret_cast<const float4*>(a)[i];
        float4 bv = reinterpret_cast<const float4*>(b)[i];
        __nv_bfloat162* pa = reinterpret_cast<__nv_bfloat162*>(g_a);
        __nv_bfloat162* pb = reinterpret_cast<__nv_bfloat162*>(g_bs);
        pa[2 * i + 0] = __floats2bfloat162_rn(av.x, av.y);
        pa[2 * i + 1] = __floats2bfloat162_rn(av.z, av.w);
        pb[2 * i + 0] = __floats2bfloat162_rn(bv.x * LOG2E, bv.y * LOG2E);
        pb[2 * i + 1] = __floats2bfloat162_rn(bv.z * LOG2E, bv.w * LOG2E);
    }
    if (i < NN) g_V[i] = 0.0f;
    if (i == 0) { g_sum = 0.0f; g_cnt = 0; g_done = 0; }
}

// ---------------- kernel 1: T[i] = sum_ALL_j 2^(a_i . bs_j) ----------------
// Grid (64 row-tiles, 9 chunks). CTA = 256 thr = 8 warps, 2 CTAs/SM.
// Double-buffered B tiles via cp.async; B fragments via ldmatrix.x4.
#define JCH 9
#define ROWB 272                      // 136 bf16 padded row, bytes
#define BUFB (128 * ROWB)             // 34816 B per tile buffer
#define SM_TOTAL (2 * BUFB)

// stage one 128x128 bf16 tile into padded smem buffer (all 256 threads)
__device__ __forceinline__ void stageB(uint32_t dstbase, const __nv_bfloat16* __restrict__ src, int tid) {
#pragma unroll
    for (int k = 0; k < 8; k++) {
        const int c   = tid + k * 256;      // 2048 chunks of 16 B
        const int row = c >> 4, col = c & 15;
        CP_ASYNC16(dstbase + row * ROWB + col * 16,
                   (const char*)(src + row * DD + col * 8));
    }
}

__global__ __launch_bounds__(256, 2) void pass1_kernel() {
    extern __shared__ char smem[];
    const uint32_t sb = smem_u32(smem);

    const int tid  = threadIdx.x;
    const int w    = tid >> 5;
    const int lane = tid & 31;
    const int g    = lane >> 2;   // row-in-8
    const int t4   = lane & 3;    // col pair
    const int wm   = w & 3;       // warp row idx -> rows 32*wm
    const int wn   = w >> 2;      // warp col idx -> cols 64*wn
    const int row_base = blockIdx.x * 128 + wm * 32;
    const int chunk    = blockIdx.y;

    // kick off staging of first tile before anything else
    stageB(sb, g_bs + (size_t)chunk * 128 * DD, tid);
    CP_COMMIT();

    // A fragments resident in registers (K=128 -> 8 k-steps, 2 m-tiles)
    uint32_t afr[2][8][4];
    const uint32_t* Aw = reinterpret_cast<const uint32_t*>(g_a);  // bf16x2 words
#pragma unroll
    for (int mt = 0; mt < 2; mt++) {
        const int r0 = row_base + 16 * mt + g;
        const int r1 = r0 + 8;
#pragma unroll
        for (int kk = 0; kk < 8; kk++) {
            const int cw = kk * 8 + t4;
            afr[mt][kk][0] = Aw[r0 * 64 + cw];
            afr[mt][kk][1] = Aw[r1 * 64 + cw];
            afr[mt][kk][2] = Aw[r0 * 64 + cw + 4];
            afr[mt][kk][3] = Aw[r1 * 64 + cw + 4];
        }
    }

    // per-lane ldmatrix offset: row (lane&7) of tile (lane>>3)
    const uint32_t lmoff = (uint32_t)((lane & 7) * ROWB + (lane >> 3) * 16);

    float vacc[2][2] = {{0.f, 0.f}, {0.f, 0.f}};

    int t = 0;
    for (int jt = chunk; jt < 64; jt += JCH, t++) {
        const int nj = jt + JCH;
        if (nj < 64) {
            stageB(sb + ((t + 1) & 1) * BUFB, g_bs + (size_t)nj * 128 * DD, tid);
            CP_COMMIT();
            CP_WAIT(1);
        } else {
            CP_WAIT(0);
        }
        __syncthreads();   // tile t visible to all warps

        const uint32_t bufb = sb + (t & 1) * BUFB;
#pragma unroll
        for (int nt = 0; nt < 8; nt++) {
            const uint32_t addr = bufb + (uint32_t)((wn * 64 + nt * 8) * ROWB) + lmoff;
            uint32_t r[4][4];
#pragma unroll
            for (int p = 0; p < 4; p++) {
                asm volatile(
                    "ldmatrix.sync.aligned.m8n8.x4.shared.b16 {%0,%1,%2,%3}, [%4];"
                    : "=r"(r[p][0]), "=r"(r[p][1]), "=r"(r[p][2]), "=r"(r[p][3])
                    : "r"(addr + p * 64));
            }
            float C[2][4] = {{0.f, 0.f, 0.f, 0.f}, {0.f, 0.f, 0.f, 0.f}};
#pragma unroll
            for (int p = 0; p < 4; p++) {
                // instr p: regs 0,1 = kk=2p (halves), regs 2,3 = kk=2p+1
                mma16816(C[0], afr[0][2 * p],     r[p][0], r[p][1]);
                mma16816(C[1], afr[1][2 * p],     r[p][0], r[p][1]);
                mma16816(C[0], afr[0][2 * p + 1], r[p][2], r[p][3]);
                mma16816(C[1], afr[1][2 * p + 1], r[p][2], r[p][3]);
            }
            // unmasked row-sum accumulate (C = S * log2e)
            vacc[0][0] += ex2f(C[0][0]) + ex2f(C[0][1]);
            vacc[0][1] += ex2f(C[0][2]) + ex2f(C[0][3]);
            vacc[1][0] += ex2f(C[1][0]) + ex2f(C[1][1]);
            vacc[1][1] += ex2f(C[1][2]) + ex2f(C[1][3]);
        }
        __syncthreads();   // done reading buf t before it is restaged
    }

    // reduce across the 4 threads of each group (same rows, different cols)
#pragma unroll
    for (int mt = 0; mt < 2; mt++) {
#pragma unroll
        for (int h = 0; h < 2; h++) {
            float v = vacc[mt][h];
            v += __shfl_xor_sync(0xffffffffu, v, 1);
            v += __shfl_xor_sync(0xffffffffu, v, 2);
            if (t4 == 0) atomicAdd(&g_V[row_base + 16 * mt + 8 * h + g], v);
        }
    }
}

// ---------------- kernel 2: per-class correction + hinge ----------------
#define MAXM 40
__global__ __launch_bounds__(256) void pass2_kernel(const float* __restrict__ a,
                                                    const float* __restrict__ b,
                                                    const int* __restrict__ labels,
                                                    float* __restrict__ out) {
    __shared__ float sa[MAXM][DD];
    __shared__ float sbuf[MAXM][DD];
    __shared__ float sD[MAXM][MAXM];
    __shared__ float sV[MAXM];
    __shared__ int   sidx[MAXM];
    __shared__ int   cnt;
    __shared__ float wsum[8];

    const int tid = threadIdx.x;
    const int c   = blockIdx.x;
    if (tid == 0) cnt = 0;
    __syncthreads();

    for (int j = tid; j < NN; j += 256) {
        if (labels[j] == c) {
            int p = atomicAdd(&cnt, 1);
            if (p < MAXM) sidx[p] = j;
        }
    }
    __syncthreads();
    const int m = (cnt < MAXM) ? cnt : MAXM;

    if (m > 0) {
        for (int k = tid; k < m * 32; k += 256) {
            const int r = k >> 5, q = k & 31;
            reinterpret_cast<float4*>(sa[r])[q]   = reinterpret_cast<const float4*>(a + sidx[r] * DD)[q];
            reinterpret_cast<float4*>(sbuf[r])[q] = reinterpret_cast<const float4*>(b + sidx[r] * DD)[q];
        }
        __syncthreads();

        const int w = tid >> 5, lane = tid & 31;
        for (int p = w; p < m * m; p += 8) {
            const int i = p / m, j = p % m;
            const float4 av = reinterpret_cast<const float4*>(sa[i])[lane];
            const float4 bv = reinterpret_cast<const float4*>(sbuf[j])[lane];
            float dot = av.x * bv.x + av.y * bv.y + av.z * bv.z + av.w * bv.w;
#pragma unroll
            for (int o = 16; o > 0; o >>= 1) dot += __shfl_xor_sync(0xffffffffu, dot, o);
            if (lane == 0) sD[i][j] = dot;
        }
        __syncthreads();

        if (tid < m) {
            float corr = 0.0f;
            for (int j = 0; j < m; j++) corr += ex2f(sD[tid][j] * LOG2E);
            sV[tid] = E1 * (g_V[sidx[tid]] - corr);
        }
        __syncthreads();

        float lsum = 0.0f;
        for (int p = tid; p < m * m; p += 256) {
            const int i = p / m, j = p % m;
            if (i != j) {
                float h = fmaxf(logf(sV[i] + sV[j]) - sD[i][j], 0.0f);
                lsum += h * h;
            }
        }
#pragma unroll
        for (int o = 16; o > 0; o >>= 1) lsum += __shfl_xor_sync(0xffffffffu, lsum, o);
        if (lane == 0) wsum[w] = lsum;
        __syncthreads();
        if (tid == 0) {
            float s = 0.0f;
#pragma unroll
            for (int k = 0; k < 8; k++) s += wsum[k];
            atomicAdd(&g_sum, s);
            atomicAdd(&g_cnt, m * (m - 1));
        }
    }

    if (tid == 0) {
        __threadfence();
        if (atomicAdd(&g_done, 1) == NCLS - 1) {
            __threadfence();
            float s = atomicAdd(&g_sum, 0.0f);
            int   n = atomicAdd(&g_cnt, 0);
            out[0] = s / (2.0f * (float)n);
        }
    }
}

// ---------------- launch ----------------
extern "C" void kernel_launch(void* const* d_in, const int* in_sizes, int n_in,
                              void* d_out, int out_size) {
    const float* a      = (const float*)d_in[0];
    const float* b      = (const float*)d_in[1];
    const int*   labels = (const int*)d_in[2];
    float* out = (float*)d_out;

    cudaFuncSetAttribute(pass1_kernel, cudaFuncAttributeMaxDynamicSharedMemorySize, SM_TOTAL);

    prep_kernel<<<(NN * DD / 4 + 255) / 256, 256>>>(a, b);
    pass1_kernel<<<dim3(64, JCH), 256, SM_TOTAL>>>();
    pass2_kernel<<<NCLS, 256>>>(a, b, labels, out);
}